// round 3
// baseline (speedup 1.0000x reference)
#include <cuda_runtime.h>
#include <math.h>

#define NLEV 3
#define NBMAX 16
#define MAXB 64
#define NCLS 80
// per-image cells per level: 3*52*52=8112, 3*26*26=2028, 3*13*13=507
#define CPI0 8112
#define CPI1 2028
#define CPI2 507
#define CPI_ALL 10647
// loss blocks per image: ceil over 256 threads
#define LB0 32
#define LB1 8
#define LB2 2
#define LBPI (LB0 + LB1 + LB2)   // 42 -> N=16 => 672 blocks (<= 148 SMs * 6)

__constant__ float c_stride[NLEV] = {8.f, 16.f, 32.f};
__constant__ float c_anchor[NLEV][3][2] = {
    {{12.f, 16.f}, {19.f, 36.f}, {40.f, 28.f}},
    {{36.f, 75.f}, {76.f, 55.f}, {72.f, 146.f}},
    {{142.f, 110.f}, {192.f, 243.f}, {459.f, 401.f}}
};

// Persistent scratch. Statically zero-initialized on module load; the
// finalize branch of each call resets everything it dirtied, so every
// graph replay starts from a clean state.
__device__ float4   g_boxes[NLEV][NBMAX][MAXB];
__device__ float    g_area [NLEV][NBMAX][MAXB];
__device__ int      g_count[NLEV][NBMAX];
__device__ double   g_acc[3];
__device__ unsigned g_arrive;
__device__ unsigned g_done;

__device__ __forceinline__ float bce_logits(float x, float t) {
    return fmaxf(x, 0.f) - x * t + __logf(1.f + __expf(-fabsf(x)));
}

__global__ void __launch_bounds__(256, 6)
k_yolo(const float* __restrict__ f0, const float* __restrict__ f1,
       const float* __restrict__ f2,
       const float* __restrict__ lab0, const float* __restrict__ lab1,
       const float* __restrict__ lab2,
       int N, float* __restrict__ out) {
    // ---------------- Phase A: gather positive boxes ----------------
    {
        const int cA = N * CPI0, cB = N * CPI1;
        const int total = N * CPI_ALL;
        const int i = blockIdx.x * 256 + threadIdx.x;
        if (i < total) {
            int lev, j, HW3;
            const float* L;
            if (i < cA)            { lev = 0; j = i;           HW3 = 8112; L = lab0; }
            else if (i < cA + cB)  { lev = 1; j = i - cA;      HW3 = 2028; L = lab1; }
            else                   { lev = 2; j = i - cA - cB; HW3 = 507;  L = lab2; }
            const float conf = __ldg(L + (size_t)j * 85 + 4);
            if (conf > 0.f) {
                const int n = j / HW3;
                const int slot = atomicAdd(&g_count[lev][n], 1);
                if (slot < MAXB) {
                    const float* p = L + (size_t)j * 85;
                    float x = p[0], y = p[1], w = p[2], h = p[3];
                    g_boxes[lev][n][slot] = make_float4(x - 0.5f * w, y - 0.5f * h,
                                                        x + 0.5f * w, y + 0.5f * h);
                    g_area[lev][n][slot] = w * h;
                }
            }
        }
    }

    // ---------------- grid-wide barrier (all blocks resident) -------
    __threadfence();
    __syncthreads();
    if (threadIdx.x == 0) {
        atomicAdd(&g_arrive, 1u);
        volatile unsigned* p = &g_arrive;
        while (*p < (unsigned)gridDim.x) { __nanosleep(32); }
        __threadfence();
    }
    __syncthreads();

    // ---------------- Phase B: loss ----------------
    const int b = blockIdx.x;
    const int n = b / LBPI;
    const int r = b - n * LBPI;
    int lev, chunk, H;
    const float* feat; const float* label;
    if (r < LB0)            { lev = 0; chunk = r;             H = 52; feat = f0; label = lab0; }
    else if (r < LB0 + LB1) { lev = 1; chunk = r - LB0;       H = 26; feat = f1; label = lab1; }
    else                    { lev = 2; chunk = r - LB0 - LB1; H = 13; feat = f2; label = lab2; }
    const int W = H, HW = H * W;

    __shared__ float4 s_box[MAXB];
    __shared__ float  s_area[MAXB];
    const int cnt = min(g_count[lev][n], MAXB);
    if (threadIdx.x < cnt) {
        s_box[threadIdx.x]  = g_boxes[lev][n][threadIdx.x];
        s_area[threadIdx.x] = g_area[lev][n][threadIdx.x];
    }
    __syncthreads();

    const int idx = chunk * 256 + threadIdx.x;   // a*HW + hw (feature-coalesced)
    float r_reg = 0.f, r_conf = 0.f, r_prob = 0.f;

    if (idx < 3 * HW) {
        const int a  = idx / HW;
        const int hw = idx - a * HW;
        const float gx = (float)(hw % W);
        const float gy = (float)(hw / W);
        const float stride = c_stride[lev];
        const float aw = c_anchor[lev][a][0];
        const float ah = c_anchor[lev][a][1];

        const float* fb = feat + ((size_t)(n * 255 + a * 85)) * HW + hw;
        const float rx = fb[0];
        const float ry = fb[(size_t)HW];
        const float rw = fb[(size_t)2 * HW];
        const float rh = fb[(size_t)3 * HW];
        const float rc = fb[(size_t)4 * HW];

        const size_t lb = ((size_t)(n * HW + hw) * 3 + a) * 85;
        const float lc = __ldg(label + lb + 4);   // L2 hit (phase A touched it)
        const bool pos = lc > 0.f;

        const float px = (__fdividef(1.f, 1.f + __expf(-rx)) + gx) * stride;
        const float py = (__fdividef(1.f, 1.f + __expf(-ry)) + gy) * stride;
        const float pw = __expf(rw) * aw;
        const float ph = __expf(rh) * ah;
        const float px1 = px - 0.5f * pw, py1 = py - 0.5f * ph;
        const float px2 = px + 0.5f * pw, py2 = py + 0.5f * ph;
        const float pa = pw * ph;

        // ignore = (max_iou < 0.5);  iou<0.5 <=> 2*inter < max(union,1e-9)
        bool ignore = true;
        #pragma unroll 4
        for (int k = 0; k < cnt; k++) {
            float4 t = s_box[k];
            float iw = fmaxf(fminf(px2, t.z) - fmaxf(px1, t.x), 0.f);
            float ih = fmaxf(fminf(py2, t.w) - fmaxf(py1, t.y), 0.f);
            float inter = iw * ih;
            float uni = fmaxf(pa + s_area[k] - inter, 1e-9f);
            if (2.f * inter >= uni) ignore = false;
        }

        const float bc = bce_logits(rc, pos ? 1.f : 0.f);
        r_conf = pos ? bc : (ignore ? bc : 0.f);

        if (pos) {   // rare path (~0.08% of cells)
            const float lx = __ldg(label + lb + 0);
            const float ly = __ldg(label + lb + 1);
            const float lw = __ldg(label + lb + 2);
            const float lh = __ldg(label + lb + 3);
            const float scale = 2.f - lw * lh * (1.f / (416.f * 416.f));
            const float inv_s = __fdividef(1.f, stride);
            const float ox = lx * inv_s - gx;
            const float oy = ly * inv_s - gy;
            float xy = bce_logits(rx, ox) + bce_logits(ry, oy);
            const float wx = __logf(__fdividef(lw, aw) + 1e-7f);
            const float wy = __logf(__fdividef(lh, ah) + 1e-7f);
            const float dwx = rw - wx, dwy = rh - wy;
            r_reg = scale * (xy + 0.5f * (dwx * dwx + dwy * dwy));

            float ps = 0.f;
            #pragma unroll 4
            for (int c = 0; c < NCLS; c++) {
                float rp = fb[(size_t)(5 + c) * HW];
                float lp = __ldg(label + lb + 5 + c);
                ps += bce_logits(rp, lp);
            }
            r_prob = ps;
        }
    }

    // ---------------- block reduction + finalize ----------------
    #pragma unroll
    for (int o = 16; o; o >>= 1) {
        r_reg  += __shfl_xor_sync(0xffffffffu, r_reg,  o);
        r_conf += __shfl_xor_sync(0xffffffffu, r_conf, o);
        r_prob += __shfl_xor_sync(0xffffffffu, r_prob, o);
    }
    __shared__ float s_r[8], s_c[8], s_p[8];
    const int warp = threadIdx.x >> 5, lane = threadIdx.x & 31;
    if (lane == 0) { s_r[warp] = r_reg; s_c[warp] = r_conf; s_p[warp] = r_prob; }
    __syncthreads();

    if (threadIdx.x == 0) {
        float R = 0.f, C = 0.f, P = 0.f;
        #pragma unroll
        for (int w = 0; w < 8; w++) { R += s_r[w]; C += s_c[w]; P += s_p[w]; }
        atomicAdd(&g_acc[0], (double)R);
        atomicAdd(&g_acc[1], (double)C);
        atomicAdd(&g_acc[2], (double)P);

        __threadfence();
        unsigned t = atomicAdd(&g_done, 1u);
        if (t == (unsigned)gridDim.x - 1u) {
            // last block: all acc adds visible; all spinners exited (they
            // incremented g_done only after leaving the barrier).
            double v0 = atomicAdd(&g_acc[0], 0.0);
            double v1 = atomicAdd(&g_acc[1], 0.0);
            double v2 = atomicAdd(&g_acc[2], 0.0);
            double invN = 1.0 / (double)N;
            out[0] = (float)(v0 * invN);
            out[1] = (float)(v1 * invN);
            out[2] = (float)(v2 * invN);
            // reset state for the next graph replay
            g_acc[0] = 0.0; g_acc[1] = 0.0; g_acc[2] = 0.0;
            #pragma unroll
            for (int l = 0; l < NLEV; l++)
                for (int m = 0; m < NBMAX; m++) g_count[l][m] = 0;
            g_arrive = 0u;
            g_done = 0u;
            __threadfence();
        }
    }
}

extern "C" void kernel_launch(void* const* d_in, const int* in_sizes, int n_in,
                              void* d_out, int out_size) {
    const float* f0 = (const float*)d_in[0];
    const float* f1 = (const float*)d_in[1];
    const float* f2 = (const float*)d_in[2];
    const float* l0 = (const float*)d_in[3];
    const float* l1 = (const float*)d_in[4];
    const float* l2 = (const float*)d_in[5];

    int N = in_sizes[0] / (255 * 52 * 52);
    if (N > NBMAX) N = NBMAX;

    k_yolo<<<N * LBPI, 256>>>(f0, f1, f2, l0, l1, l2, N, (float*)d_out);
}

// round 4
// speedup vs baseline: 1.0274x; 1.0274x over previous
#include <cuda_runtime.h>
#include <math.h>

#define NLEV 3
#define NBMAX 16
#define MAXB 64
#define NCLS 80
// loss/gather blocks per image-level: ceil(3*HW/256)
#define LB0 32
#define LB1 8
#define LB2 2
#define LBPI (LB0 + LB1 + LB2)   // 42 -> N=16 => 672 blocks (co-resident @6/SM)

__constant__ float c_stride[NLEV] = {8.f, 16.f, 32.f};
__constant__ float c_anchor[NLEV][3][2] = {
    {{12.f, 16.f}, {19.f, 36.f}, {40.f, 28.f}},
    {{36.f, 75.f}, {76.f, 55.f}, {72.f, 146.f}},
    {{142.f, 110.f}, {192.f, 243.f}, {459.f, 401.f}}
};
__constant__ int c_grpsize[NLEV] = {LB0, LB1, LB2};

// Persistent scratch; statically zero-initialized, and the finalize branch
// resets everything it dirtied so each graph replay starts clean.
__device__ float4   g_boxes[NLEV][NBMAX][MAXB];
__device__ float    g_area [NLEV][NBMAX][MAXB];
__device__ int      g_count[NLEV][NBMAX];
__device__ unsigned g_grp  [NLEV][NBMAX];   // per-(lev,image) arrival counters
__device__ double   g_acc[3];
__device__ unsigned g_done;

__device__ __forceinline__ float bce_logits(float x, float t) {
    return fmaxf(x, 0.f) - x * t + __logf(1.f + __expf(-fabsf(x)));
}

__global__ void __launch_bounds__(256, 6)
k_yolo(const float* __restrict__ f0, const float* __restrict__ f1,
       const float* __restrict__ f2,
       const float* __restrict__ lab0, const float* __restrict__ lab1,
       const float* __restrict__ lab2,
       int N, float* __restrict__ out) {
    // decode (image n, level, chunk)
    const int b = blockIdx.x;
    const int n = b / LBPI;
    const int r = b - n * LBPI;
    int lev, chunk, H;
    const float* feat; const float* label;
    if (r < LB0)            { lev = 0; chunk = r;             H = 52; feat = f0; label = lab0; }
    else if (r < LB0 + LB1) { lev = 1; chunk = r - LB0;       H = 26; feat = f1; label = lab1; }
    else                    { lev = 2; chunk = r - LB0 - LB1; H = 13; feat = f2; label = lab2; }
    const int W = H, HW = H * W;

    const int idx = chunk * 256 + threadIdx.x;   // a*HW + hw (feature-coalesced)
    const bool active = idx < 3 * HW;

    // ---- Phase A: load conf + features for MY cell; gather positives ----
    int a = 0, hw = 0;
    size_t lb = 0;
    float lc = 0.f, rx = 0.f, ry = 0.f, rw = 0.f, rh = 0.f, rc = 0.f;
    if (active) {
        a  = idx / HW;
        hw = idx - a * HW;
        lb = ((size_t)(n * HW + hw) * 3 + a) * 85;
        lc = __ldg(label + lb + 4);

        const float* fb = feat + ((size_t)(n * 255 + a * 85)) * HW + hw;
        rx = fb[0];
        ry = fb[(size_t)HW];
        rw = fb[(size_t)2 * HW];
        rh = fb[(size_t)3 * HW];
        rc = fb[(size_t)4 * HW];

        if (lc > 0.f) {
            const float x = __ldg(label + lb + 0);
            const float y = __ldg(label + lb + 1);
            const float w = __ldg(label + lb + 2);
            const float h = __ldg(label + lb + 3);
            const int slot = atomicAdd(&g_count[lev][n], 1);
            if (slot < MAXB) {
                g_boxes[lev][n][slot] = make_float4(x - 0.5f * w, y - 0.5f * h,
                                                    x + 0.5f * w, y + 0.5f * h);
                g_area[lev][n][slot] = w * h;
            }
        }
    }

    // ---- per-(lev,image) group barrier (32/8/2 blocks) ----
    __threadfence();
    __syncthreads();
    if (threadIdx.x == 0) {
        const unsigned gs = (unsigned)c_grpsize[lev];
        atomicAdd(&g_grp[lev][n], 1u);
        volatile unsigned* p = &g_grp[lev][n];
        while (*p < gs) { }
        __threadfence();
    }
    __syncthreads();

    // ---- load this group's boxes into smem ----
    __shared__ float4 s_box[MAXB];
    __shared__ float  s_area[MAXB];
    const int cnt = min(g_count[lev][n], MAXB);
    if (threadIdx.x < cnt) {
        s_box[threadIdx.x]  = g_boxes[lev][n][threadIdx.x];
        s_area[threadIdx.x] = g_area[lev][n][threadIdx.x];
    }
    __syncthreads();

    // ---- Phase B: loss ----
    float r_reg = 0.f, r_conf = 0.f, r_prob = 0.f;
    if (active) {
        const float gx = (float)(hw % W);
        const float gy = (float)(hw / W);
        const float stride = c_stride[lev];
        const float aw = c_anchor[lev][a][0];
        const float ah = c_anchor[lev][a][1];
        const bool pos = lc > 0.f;

        const float px = (__fdividef(1.f, 1.f + __expf(-rx)) + gx) * stride;
        const float py = (__fdividef(1.f, 1.f + __expf(-ry)) + gy) * stride;
        const float pw = __expf(rw) * aw;
        const float ph = __expf(rh) * ah;
        const float px1 = px - 0.5f * pw, py1 = py - 0.5f * ph;
        const float px2 = px + 0.5f * pw, py2 = py + 0.5f * ph;
        const float pa = pw * ph;

        // ignore = (max_iou < 0.5);  iou<0.5 <=> 2*inter < max(union,1e-9)
        bool ignore = true;
        #pragma unroll 4
        for (int k = 0; k < cnt; k++) {
            float4 t = s_box[k];
            float iw = fmaxf(fminf(px2, t.z) - fmaxf(px1, t.x), 0.f);
            float ih = fmaxf(fminf(py2, t.w) - fmaxf(py1, t.y), 0.f);
            float inter = iw * ih;
            float uni = fmaxf(pa + s_area[k] - inter, 1e-9f);
            if (2.f * inter >= uni) ignore = false;
        }

        const float bc = bce_logits(rc, pos ? 1.f : 0.f);
        r_conf = pos ? bc : (ignore ? bc : 0.f);

        if (pos) {   // rare path (~0.08% of cells)
            const float lx = __ldg(label + lb + 0);
            const float ly = __ldg(label + lb + 1);
            const float lw = __ldg(label + lb + 2);
            const float lh = __ldg(label + lb + 3);
            const float scale = 2.f - lw * lh * (1.f / (416.f * 416.f));
            const float inv_s = __fdividef(1.f, stride);
            const float ox = lx * inv_s - gx;
            const float oy = ly * inv_s - gy;
            float xy = bce_logits(rx, ox) + bce_logits(ry, oy);
            const float wx = __logf(__fdividef(lw, aw) + 1e-7f);
            const float wy = __logf(__fdividef(lh, ah) + 1e-7f);
            const float dwx = rw - wx, dwy = rh - wy;
            r_reg = scale * (xy + 0.5f * (dwx * dwx + dwy * dwy));

            const float* fb = feat + ((size_t)(n * 255 + a * 85)) * HW + hw;
            float ps = 0.f;
            #pragma unroll 4
            for (int c = 0; c < NCLS; c++) {
                float rp = fb[(size_t)(5 + c) * HW];
                float lp = __ldg(label + lb + 5 + c);
                ps += bce_logits(rp, lp);
            }
            r_prob = ps;
        }
    }

    // ---- block reduction + last-block finalize ----
    #pragma unroll
    for (int o = 16; o; o >>= 1) {
        r_reg  += __shfl_xor_sync(0xffffffffu, r_reg,  o);
        r_conf += __shfl_xor_sync(0xffffffffu, r_conf, o);
        r_prob += __shfl_xor_sync(0xffffffffu, r_prob, o);
    }
    __shared__ float s_r[8], s_c[8], s_p[8];
    const int warp = threadIdx.x >> 5, lane = threadIdx.x & 31;
    if (lane == 0) { s_r[warp] = r_reg; s_c[warp] = r_conf; s_p[warp] = r_prob; }
    __syncthreads();

    if (threadIdx.x == 0) {
        float R = 0.f, C = 0.f, P = 0.f;
        #pragma unroll
        for (int w = 0; w < 8; w++) { R += s_r[w]; C += s_c[w]; P += s_p[w]; }
        atomicAdd(&g_acc[0], (double)R);
        atomicAdd(&g_acc[1], (double)C);
        atomicAdd(&g_acc[2], (double)P);

        __threadfence();
        unsigned t = atomicAdd(&g_done, 1u);
        if (t == (unsigned)gridDim.x - 1u) {
            // all blocks done: every group barrier fully drained, all acc
            // adds visible. Write output and reset state for next replay.
            double v0 = atomicAdd(&g_acc[0], 0.0);
            double v1 = atomicAdd(&g_acc[1], 0.0);
            double v2 = atomicAdd(&g_acc[2], 0.0);
            double invN = 1.0 / (double)N;
            out[0] = (float)(v0 * invN);
            out[1] = (float)(v1 * invN);
            out[2] = (float)(v2 * invN);
            g_acc[0] = 0.0; g_acc[1] = 0.0; g_acc[2] = 0.0;
            #pragma unroll
            for (int l = 0; l < NLEV; l++)
                #pragma unroll
                for (int m = 0; m < NBMAX; m++) { g_count[l][m] = 0; g_grp[l][m] = 0u; }
            g_done = 0u;
            __threadfence();
        }
    }
}

extern "C" void kernel_launch(void* const* d_in, const int* in_sizes, int n_in,
                              void* d_out, int out_size) {
    const float* f0 = (const float*)d_in[0];
    const float* f1 = (const float*)d_in[1];
    const float* f2 = (const float*)d_in[2];
    const float* l0 = (const float*)d_in[3];
    const float* l1 = (const float*)d_in[4];
    const float* l2 = (const float*)d_in[5];

    int N = in_sizes[0] / (255 * 52 * 52);
    if (N > NBMAX) N = NBMAX;

    k_yolo<<<N * LBPI, 256>>>(f0, f1, f2, l0, l1, l2, N, (float*)d_out);
}